// round 15
// baseline (speedup 1.0000x reference)
#include <cuda_runtime.h>
#include <cuda_fp16.h>

#define NMAX   100000
#define EMAX   1200000
#define NGRAPH 64
#define D      64
#define NBLK_SCAN 128   // >= ceil(NMAX/1024)

// ---------------- device scratch (no allocations allowed) ----------------
// INVARIANT at entry of every call: g_cntI==0, g_pooled==0, g_cnt==0, g_done==0,
// g_barCnt==0. g_barGen is monotonic (never reset; output-invariant).
// g_lbFlag is reset by k_cntscan phase 0 before the scan phase reads it.
__device__ __align__(16) __half g_hH[(size_t)NMAX * D];   // pre-agg rows (fp16)
__device__ __align__(16) __half g_hG[(size_t)NMAX * D];   // h1 rows (fp16)
__device__ float g_dinv[NMAX];
__device__ __align__(16) float g_pooled[NGRAPH * D];
__device__ float g_cnt[NGRAPH];
__device__ float g_sc1[D], g_sh1[D], g_sc2[D], g_sh2[D];

__device__ int g_cntI[NMAX];
__device__ int g_offs[NMAX + 1];
__device__ int g_cursor[NMAX];
__device__ __align__(16) int g_csrc[EMAX];
__device__ volatile unsigned g_lbFlag[NBLK_SCAN];  // status(2b)<<30 | sum
__device__ unsigned g_done;
__device__ unsigned g_barCnt;
__device__ volatile unsigned g_barGen;

// ---------------- grid barrier (all blocks co-resident: <=98 blocks) -------
__device__ __forceinline__ void gbar(int NB) {
    __syncthreads();
    if (threadIdx.x == 0) {
        __threadfence();
        unsigned gen = g_barGen;
        unsigned t = atomicAdd(&g_barCnt, 1u);
        if (t == (unsigned)NB - 1u) {
            g_barCnt = 0;
            __threadfence();
            g_barGen = gen + 1u;
        } else {
            while (g_barGen == gen) __nanosleep(64);
        }
        __threadfence();
    }
    __syncthreads();
}

__device__ __forceinline__ void red_add_v4(float* addr, float a, float b,
                                           float c, float d) {
    asm volatile("red.global.add.v4.f32 [%0], {%1,%2,%3,%4};"
                 :: "l"(addr), "f"(a), "f"(b), "f"(c), "f"(d) : "memory");
}

__device__ __forceinline__ void red_add_i(int* addr, int v) {
    asm volatile("red.global.add.s32 [%0], %1;" :: "l"(addr), "r"(v) : "memory");
}

__device__ __forceinline__ float2 h2f(unsigned raw) {
    return __half22float2(*(__half2*)&raw);
}

__device__ __forceinline__ unsigned f2h(float a, float b) {
    __half2 p = __floats2half2_rn(a, b);
    return *(unsigned*)&p;
}

__device__ __forceinline__ uint2 f4_to_h4(float a, float b, float c, float d) {
    uint2 u;
    u.x = f2h(a, b);
    u.y = f2h(c, d);
    return u;
}

// accumulate 8 halves (uint4) into acc[8], weighted / unweighted
__device__ __forceinline__ void acc8_w(float* acc, uint4 r, float wt) {
    float2 p0 = h2f(r.x), p1 = h2f(r.y), p2 = h2f(r.z), p3 = h2f(r.w);
    acc[0] = fmaf(wt, p0.x, acc[0]); acc[1] = fmaf(wt, p0.y, acc[1]);
    acc[2] = fmaf(wt, p1.x, acc[2]); acc[3] = fmaf(wt, p1.y, acc[3]);
    acc[4] = fmaf(wt, p2.x, acc[4]); acc[5] = fmaf(wt, p2.y, acc[5]);
    acc[6] = fmaf(wt, p3.x, acc[6]); acc[7] = fmaf(wt, p3.y, acc[7]);
}

__device__ __forceinline__ void acc8(float* acc, uint4 r) {
    float2 p0 = h2f(r.x), p1 = h2f(r.y), p2 = h2f(r.z), p3 = h2f(r.w);
    acc[0] += p0.x; acc[1] += p0.y; acc[2] += p1.x; acc[3] += p1.y;
    acc[4] += p2.x; acc[5] += p2.y; acc[6] += p3.x; acc[7] += p3.y;
}

__device__ __forceinline__ void mma16816(float* c, unsigned a0, unsigned a1,
                                         unsigned a2, unsigned a3,
                                         unsigned b0, unsigned b1) {
    asm volatile(
        "mma.sync.aligned.m16n8k16.row.col.f32.f16.f16.f32 "
        "{%0,%1,%2,%3}, {%4,%5,%6,%7}, {%8,%9}, {%0,%1,%2,%3};"
        : "+f"(c[0]), "+f"(c[1]), "+f"(c[2]), "+f"(c[3])
        : "r"(a0), "r"(a1), "r"(a2), "r"(a3), "r"(b0), "r"(b1));
}

// ======= cnt (phase 0, grid-stride, red atomics) + gbar + look-back scan ===
__global__ void __launch_bounds__(256) k_cntscan(
        const int* __restrict__ dst,
        const float* __restrict__ b1, const float* __restrict__ g1,
        const float* __restrict__ be1, const float* __restrict__ m1,
        const float* __restrict__ v1,
        const float* __restrict__ b2, const float* __restrict__ g2,
        const float* __restrict__ be2, const float* __restrict__ m2,
        const float* __restrict__ v2, int N, int E, int NB) {
    int tid = threadIdx.x, bid = blockIdx.x;

    // ---- phase 0: histogram + lbFlag reset ----
    if (bid == 0 && tid < NBLK_SCAN) g_lbFlag[tid] = 0;
    {
        int stride4 = NB * 256 * 4;
        for (int e4 = (bid * 256 + tid) * 4; e4 < E; e4 += stride4) {
            if (e4 + 3 < E) {
                int4 d4 = *(const int4*)(dst + e4);
                red_add_i(&g_cntI[d4.x], 1);
                red_add_i(&g_cntI[d4.y], 1);
                red_add_i(&g_cntI[d4.z], 1);
                red_add_i(&g_cntI[d4.w], 1);
            } else {
                for (int e = e4; e < E; e++)
                    red_add_i(&g_cntI[dst[e]], 1);
            }
        }
    }
    gbar(NB);

    // ---- phase 1: decoupled look-back scan + dinv + BN fold + cntI reset ---
    __shared__ int wsum[8];
    __shared__ unsigned exS;
    __shared__ int totS;
    int lane = tid & 31, w = tid >> 5;
    int base = bid * 1024 + tid * 4;

    int v0 = 0, vv1 = 0, vv2 = 0, vv3 = 0;
    if (base + 0 < N) v0  = g_cntI[base + 0];
    if (base + 1 < N) vv1 = g_cntI[base + 1];
    if (base + 2 < N) vv2 = g_cntI[base + 2];
    if (base + 3 < N) vv3 = g_cntI[base + 3];
    int s = v0 + vv1 + vv2 + vv3;

    int inc = s;
#pragma unroll
    for (int o = 1; o < 32; o <<= 1) {
        int y = __shfl_up_sync(0xffffffff, inc, o);
        if (lane >= o) inc += y;
    }
    if (lane == 31) wsum[w] = inc;
    __syncthreads();
    if (tid == 0) {
        int run = 0;
#pragma unroll
        for (int i = 0; i < 8; i++) { int xv = wsum[i]; wsum[i] = run; run += xv; }
        totS = run;
        unsigned pack = (bid == 0 ? (2u << 30) : (1u << 30)) | (unsigned)run;
        atomicExch((unsigned*)&g_lbFlag[bid], pack);
    }
    __syncthreads();
    int blkEx = wsum[w] + inc - s;
    int total = totS;

    if (bid > 0) {
        if (w == 0) {
            unsigned ex = 0;
            int wnd = bid;
            for (;;) {
                int idx = wnd - 32 + lane;
                unsigned f = (1u << 30);
                if (idx >= 0) {
                    do { f = g_lbFlag[idx]; } while ((f >> 30) == 0);
                }
                unsigned isPref = __ballot_sync(0xffffffff, idx >= 0 && (f >> 30) == 2u);
                int cut = isPref ? (31 - __clz(isPref)) : -1;
                unsigned val = (lane >= cut) ? (f & 0x3FFFFFFFu) : 0u;
#pragma unroll
                for (int o = 16; o; o >>= 1) val += __shfl_down_sync(0xffffffff, val, o);
                if (lane == 0) ex += val;
                if (cut >= 0) break;
                wnd -= 32;
            }
            if (lane == 0) {
                exS = ex;
                atomicExch((unsigned*)&g_lbFlag[bid], (2u << 30) | (ex + (unsigned)total));
            }
        }
        __syncthreads();
    } else if (tid == 0) {
        exS = 0;
    }
    __syncthreads();
    unsigned ex = exS;

    int o = (int)ex + blkEx;
    if (base + 0 < N) { g_offs[base+0]=o; g_cursor[base+0]=o; g_dinv[base+0]=rsqrtf((float)v0 +1.f); g_cntI[base+0]=0; o+=v0;  }
    if (base + 1 < N) { g_offs[base+1]=o; g_cursor[base+1]=o; g_dinv[base+1]=rsqrtf((float)vv1+1.f); g_cntI[base+1]=0; o+=vv1; }
    if (base + 2 < N) { g_offs[base+2]=o; g_cursor[base+2]=o; g_dinv[base+2]=rsqrtf((float)vv2+1.f); g_cntI[base+2]=0; o+=vv2; }
    if (base + 3 < N) { g_offs[base+3]=o; g_cursor[base+3]=o; g_dinv[base+3]=rsqrtf((float)vv3+1.f); g_cntI[base+3]=0; }

    if (bid == 0 && tid == 0) g_offs[N] = E;
    if (bid == 0 && tid < D) {
        float s1 = g1[tid] * rsqrtf(v1[tid] + 1e-5f);
        g_sc1[tid] = s1;
        g_sh1[tid] = (b1[tid] - m1[tid]) * s1 + be1[tid];
        float s2 = g2[tid] * rsqrtf(v2[tid] + 1e-5f);
        g_sc2[tid] = s2;
        g_sh2[tid] = (b2[tid] - m2[tid]) * s2 + be2[tid];
    }
}

// ------- fill CSR: 4 edges/thread via int4 ---------------------------------
__global__ void k_fill(const int* __restrict__ src, const int* __restrict__ dst, int E) {
    int base = (blockIdx.x * blockDim.x + threadIdx.x) * 4;
    if (base + 3 < E) {
        int4 d4 = *(const int4*)(dst + base);
        int4 s4 = *(const int4*)(src + base);
        int p0 = atomicAdd(&g_cursor[d4.x], 1);
        int p1 = atomicAdd(&g_cursor[d4.y], 1);
        int p2 = atomicAdd(&g_cursor[d4.z], 1);
        int p3 = atomicAdd(&g_cursor[d4.w], 1);
        g_csrc[p0] = s4.x;
        g_csrc[p1] = s4.y;
        g_csrc[p2] = s4.z;
        g_csrc[p3] = s4.w;
    } else {
        for (int e = base; e < E; e++) {
            int d = dst[e];
            int p = atomicAdd(&g_cursor[d], 1);
            g_csrc[p] = src[e];
        }
    }
}

// ---------------- GEMM1 core macro ----------------
#define GEMM_ROW(ai, i)                                                           \
    acc[i][0] = fmaf(ai.w, w3.x, fmaf(ai.z, w2.x, fmaf(ai.y, w1.x, fmaf(ai.x, w0.x, acc[i][0])))); \
    acc[i][1] = fmaf(ai.w, w3.y, fmaf(ai.z, w2.y, fmaf(ai.y, w1.y, fmaf(ai.x, w0.y, acc[i][1])))); \
    acc[i][2] = fmaf(ai.w, w3.z, fmaf(ai.z, w2.z, fmaf(ai.y, w1.z, fmaf(ai.x, w0.z, acc[i][2])))); \
    acc[i][3] = fmaf(ai.w, w3.w, fmaf(ai.z, w2.w, fmaf(ai.y, w1.w, fmaf(ai.x, w0.w, acc[i][3]))));

// ------- GEMM1: C_h[N,64] = fp16(A_f32 @ W1) (runs ∥ cntscan+fill) ---------
__global__ void __launch_bounds__(256) k_gemm1(const float* __restrict__ A,
                                               const float* __restrict__ W,
                                               __half* __restrict__ C, int N) {
    __shared__ __align__(16) float Ws[D * D];
    __shared__ __align__(16) float As[64 * 68];
    int tid = threadIdx.x;
    int row0 = blockIdx.x * 64;

    float4* Ws4 = (float4*)Ws;
    const float4* W4 = (const float4*)W;
#pragma unroll
    for (int i = 0; i < 4; i++) Ws4[tid + i * 256] = W4[tid + i * 256];

#pragma unroll
    for (int i = 0; i < 4; i++) {
        int idx = tid + i * 256;
        int r = idx >> 4, c4 = idx & 15;
        float4 a = make_float4(0.f, 0.f, 0.f, 0.f);
        if (row0 + r < N)
            a = __ldcs((const float4*)(A + (size_t)(row0 + r) * D) + c4);
        ((float4*)&As[r * 68])[c4] = a;
    }
    __syncthreads();

    int tx = tid & 15, ty = tid >> 4;
    float acc[4][4];
#pragma unroll
    for (int i = 0; i < 4; i++)
#pragma unroll
        for (int j = 0; j < 4; j++) acc[i][j] = 0.f;

    const float4* A0 = (const float4*)&As[(ty * 4 + 0) * 68];
    const float4* A1 = (const float4*)&As[(ty * 4 + 1) * 68];
    const float4* A2 = (const float4*)&As[(ty * 4 + 2) * 68];
    const float4* A3 = (const float4*)&As[(ty * 4 + 3) * 68];

#pragma unroll
    for (int k4 = 0; k4 < 16; k4++) {
        float4 w0 = Ws4[(4 * k4 + 0) * 16 + tx];
        float4 w1 = Ws4[(4 * k4 + 1) * 16 + tx];
        float4 w2 = Ws4[(4 * k4 + 2) * 16 + tx];
        float4 w3 = Ws4[(4 * k4 + 3) * 16 + tx];
        float4 a0 = A0[k4], a1 = A1[k4], a2 = A2[k4], a3 = A3[k4];
        GEMM_ROW(a0, 0)
        GEMM_ROW(a1, 1)
        GEMM_ROW(a2, 2)
        GEMM_ROW(a3, 3)
    }

#pragma unroll
    for (int i = 0; i < 4; i++) {
        int r = row0 + ty * 4 + i;
        if (r < N)
            ((uint2*)(C + (size_t)r * D))[tx] =
                f4_to_h4(acc[i][0], acc[i][1], acc[i][2], acc[i][3]);
    }
}

// -------- layer-1 gather: 8 threads/node, uint4 (16B) lanes (PROFILED) -----
__global__ void __launch_bounds__(256) k_agg1(int N) {
    int t = blockIdx.x * blockDim.x + threadIdx.x;
    int node = t >> 3;
    if (node >= N) return;
    int c8 = t & 7;
    const uint4* hp = (const uint4*)g_hH;   // row = 8 uint4
    float dd = g_dinv[node];
    float acc[8];
    {
        uint4 sr = hp[(size_t)node * 8 + c8];
        float2 p0 = h2f(sr.x), p1 = h2f(sr.y), p2 = h2f(sr.z), p3 = h2f(sr.w);
        acc[0] = dd * p0.x; acc[1] = dd * p0.y;
        acc[2] = dd * p1.x; acc[3] = dd * p1.y;
        acc[4] = dd * p2.x; acc[5] = dd * p2.y;
        acc[6] = dd * p3.x; acc[7] = dd * p3.y;
    }
    int beg = g_offs[node], end = g_offs[node + 1];
    int j = beg;
    for (; j + 3 < end; j += 4) {
        int i0 = __ldg(&g_csrc[j + 0]);
        int i1 = __ldg(&g_csrc[j + 1]);
        int i2 = __ldg(&g_csrc[j + 2]);
        int i3 = __ldg(&g_csrc[j + 3]);
        float w0 = __ldg(&g_dinv[i0]);
        float w1 = __ldg(&g_dinv[i1]);
        float w2 = __ldg(&g_dinv[i2]);
        float w3 = __ldg(&g_dinv[i3]);
        uint4 r0 = __ldg(&hp[(size_t)i0 * 8 + c8]);
        uint4 r1 = __ldg(&hp[(size_t)i1 * 8 + c8]);
        uint4 r2 = __ldg(&hp[(size_t)i2 * 8 + c8]);
        uint4 r3 = __ldg(&hp[(size_t)i3 * 8 + c8]);
        acc8_w(acc, r0, w0);
        acc8_w(acc, r1, w1);
        acc8_w(acc, r2, w2);
        acc8_w(acc, r3, w3);
    }
    for (; j < end; j++) {
        int i0 = __ldg(&g_csrc[j]);
        float w0 = __ldg(&g_dinv[i0]);
        uint4 r0 = __ldg(&hp[(size_t)i0 * 8 + c8]);
        acc8_w(acc, r0, w0);
    }
    int c = c8 * 8;
    uint4 outv;
    {
        float y0 = fmaxf(0.f, acc[0] * dd * g_sc1[c + 0] + g_sh1[c + 0]);
        float y1 = fmaxf(0.f, acc[1] * dd * g_sc1[c + 1] + g_sh1[c + 1]);
        float y2 = fmaxf(0.f, acc[2] * dd * g_sc1[c + 2] + g_sh1[c + 2]);
        float y3 = fmaxf(0.f, acc[3] * dd * g_sc1[c + 3] + g_sh1[c + 3]);
        float y4 = fmaxf(0.f, acc[4] * dd * g_sc1[c + 4] + g_sh1[c + 4]);
        float y5 = fmaxf(0.f, acc[5] * dd * g_sc1[c + 5] + g_sh1[c + 5]);
        float y6 = fmaxf(0.f, acc[6] * dd * g_sc1[c + 6] + g_sh1[c + 6]);
        float y7 = fmaxf(0.f, acc[7] * dd * g_sc1[c + 7] + g_sh1[c + 7]);
        outv.x = f2h(y0, y1); outv.y = f2h(y2, y3);
        outv.z = f2h(y4, y5); outv.w = f2h(y6, y7);
    }
    ((uint4*)g_hG)[(size_t)node * 8 + c8] = outv;
}

// ------- GEMM2 tensor-core: hH = fp16((hG @ W2) * dinv), W2 split hi+res ---
__global__ void __launch_bounds__(256) k_gemm2tc(const __half* __restrict__ A,
                                                 const float* __restrict__ W,
                                                 __half* __restrict__ C, int N) {
    __shared__ __align__(16) __half As[128 * 72];
    __shared__ __align__(16) __half Wh[64 * 72];
    __shared__ __align__(16) __half Wr[64 * 72];
    int tid = threadIdx.x;
    int warp = tid >> 5, lane = tid & 31;
    int row0 = blockIdx.x * 128;

#pragma unroll
    for (int i = 0; i < 16; i++) {
        int idx = tid + i * 256;
        int k = idx >> 6, n = idx & 63;
        float w = W[k * 64 + n];
        __half wh = __float2half_rn(w);
        Wh[n * 72 + k] = wh;
        Wr[n * 72 + k] = __float2half_rn(w - __half2float(wh));
    }

#pragma unroll
    for (int i = 0; i < 4; i++) {
        int idx = tid + i * 256;
        int r = idx >> 3, c8 = idx & 7;
        uint4 raw = make_uint4(0u, 0u, 0u, 0u);
        if (row0 + r < N)
            raw = __ldcs((const uint4*)(A + (size_t)(row0 + r) * D) + c8);
        *(uint4*)&As[r * 72 + c8 * 8] = raw;
    }
    __syncthreads();

    int g = lane >> 2, tg = lane & 3;
    int rbase = warp * 16;
    float acc[8][4];
#pragma unroll
    for (int nt = 0; nt < 8; nt++)
#pragma unroll
        for (int i = 0; i < 4; i++) acc[nt][i] = 0.f;

#pragma unroll
    for (int k0 = 0; k0 < 64; k0 += 16) {
        unsigned ra0 = *(const unsigned*)&As[(rbase + g) * 72 + k0 + tg * 2];
        unsigned ra1 = *(const unsigned*)&As[(rbase + g + 8) * 72 + k0 + tg * 2];
        unsigned ra2 = *(const unsigned*)&As[(rbase + g) * 72 + k0 + tg * 2 + 8];
        unsigned ra3 = *(const unsigned*)&As[(rbase + g + 8) * 72 + k0 + tg * 2 + 8];
#pragma unroll
        for (int nt = 0; nt < 8; nt++) {
            int nrow = (nt * 8 + g) * 72 + k0 + tg * 2;
            unsigned bh0 = *(const unsigned*)&Wh[nrow];
            unsigned bh1 = *(const unsigned*)&Wh[nrow + 8];
            mma16816(acc[nt], ra0, ra1, ra2, ra3, bh0, bh1);
            unsigned br0 = *(const unsigned*)&Wr[nrow];
            unsigned br1 = *(const unsigned*)&Wr[nrow + 8];
            mma16816(acc[nt], ra0, ra1, ra2, ra3, br0, br1);
        }
    }

    int r0g = row0 + rbase + g;
    int r1g = r0g + 8;
    float d0 = (r0g < N) ? g_dinv[r0g] : 0.f;
    float d1 = (r1g < N) ? g_dinv[r1g] : 0.f;
#pragma unroll
    for (int nt = 0; nt < 8; nt++) {
        int n = nt * 8 + tg * 2;
        if (r0g < N)
            *(unsigned*)(C + (size_t)r0g * D + n) = f2h(acc[nt][0] * d0, acc[nt][1] * d0);
        if (r1g < N)
            *(unsigned*)(C + (size_t)r1g * D + n) = f2h(acc[nt][2] * d1, acc[nt][3] * d1);
    }
}

// ------- agg2 (8T/node uint4) + BN2 + ReLU + pool + last-block classifier --
__global__ void __launch_bounds__(256) k_agg2cls(const int* __restrict__ batch,
                                                 const float* __restrict__ Wc,
                                                 const float* __restrict__ bc,
                                                 float* __restrict__ out, int N) {
    __shared__ int isLast;
    int t = blockIdx.x * blockDim.x + threadIdx.x;
    int tid = threadIdx.x;
    int node = t >> 3;
    if (node < N) {
        int c8 = t & 7;
        const uint4* hp = (const uint4*)g_hH;
        float acc[8];
        {
            uint4 sr = hp[(size_t)node * 8 + c8];
            float2 p0 = h2f(sr.x), p1 = h2f(sr.y), p2 = h2f(sr.z), p3 = h2f(sr.w);
            acc[0] = p0.x; acc[1] = p0.y; acc[2] = p1.x; acc[3] = p1.y;
            acc[4] = p2.x; acc[5] = p2.y; acc[6] = p3.x; acc[7] = p3.y;
        }
        int beg = g_offs[node], end = g_offs[node + 1];
        int j = beg;
        for (; j + 3 < end; j += 4) {
            int i0 = __ldg(&g_csrc[j + 0]);
            int i1 = __ldg(&g_csrc[j + 1]);
            int i2 = __ldg(&g_csrc[j + 2]);
            int i3 = __ldg(&g_csrc[j + 3]);
            uint4 r0 = __ldg(&hp[(size_t)i0 * 8 + c8]);
            uint4 r1 = __ldg(&hp[(size_t)i1 * 8 + c8]);
            uint4 r2 = __ldg(&hp[(size_t)i2 * 8 + c8]);
            uint4 r3 = __ldg(&hp[(size_t)i3 * 8 + c8]);
            acc8(acc, r0);
            acc8(acc, r1);
            acc8(acc, r2);
            acc8(acc, r3);
        }
        for (; j < end; j++) {
            int i0 = __ldg(&g_csrc[j]);
            uint4 r0 = __ldg(&hp[(size_t)i0 * 8 + c8]);
            acc8(acc, r0);
        }
        float dd = g_dinv[node];
        int c = c8 * 8;
        float y0 = fmaxf(0.f, acc[0] * dd * g_sc2[c + 0] + g_sh2[c + 0]);
        float y1 = fmaxf(0.f, acc[1] * dd * g_sc2[c + 1] + g_sh2[c + 1]);
        float y2 = fmaxf(0.f, acc[2] * dd * g_sc2[c + 2] + g_sh2[c + 2]);
        float y3 = fmaxf(0.f, acc[3] * dd * g_sc2[c + 3] + g_sh2[c + 3]);
        float y4 = fmaxf(0.f, acc[4] * dd * g_sc2[c + 4] + g_sh2[c + 4]);
        float y5 = fmaxf(0.f, acc[5] * dd * g_sc2[c + 5] + g_sh2[c + 5]);
        float y6 = fmaxf(0.f, acc[6] * dd * g_sc2[c + 6] + g_sh2[c + 6]);
        float y7 = fmaxf(0.f, acc[7] * dd * g_sc2[c + 7] + g_sh2[c + 7]);
        int g = batch[node];
        red_add_v4(&g_pooled[g * D + c + 0], y0, y1, y2, y3);
        red_add_v4(&g_pooled[g * D + c + 4], y4, y5, y6, y7);
        if (c8 == 0) atomicAdd(&g_cnt[g], 1.0f);
    }

    __threadfence();
    __syncthreads();
    if (tid == 0) {
        unsigned old = atomicAdd(&g_done, 1u);
        isLast = (old == gridDim.x - 1u) ? 1 : 0;
    }
    __syncthreads();
    if (isLast) {
        __threadfence();
        if (tid < NGRAPH * 2) {
            int g = tid >> 1, o = tid & 1;
            float inv = 1.f / fmaxf(g_cnt[g], 1.f);
            float s = 0.f;
#pragma unroll
            for (int d = 0; d < D; d++) s += g_pooled[g * D + d] * Wc[d * 2 + o];
            out[tid] = s * inv + bc[o];
        }
        __syncthreads();
        for (int i = tid; i < NGRAPH * D; i += 256) g_pooled[i] = 0.f;
        if (tid < NGRAPH) g_cnt[tid] = 0.f;
        if (tid == 0) g_done = 0;
    }
}

// ---------------- host orchestration (fork/join, 6 launches) ---------------
extern "C" void kernel_launch(void* const* d_in, const int* in_sizes, int n_in,
                              void* d_out, int out_size) {
    const float* x   = (const float*)d_in[0];
    const int*   ei  = (const int*)d_in[1];
    const int*   bat = (const int*)d_in[2];
    const float* W1  = (const float*)d_in[3];
    const float* b1  = (const float*)d_in[4];
    const float* g1  = (const float*)d_in[5];
    const float* be1 = (const float*)d_in[6];
    const float* m1  = (const float*)d_in[7];
    const float* v1  = (const float*)d_in[8];
    const float* W2  = (const float*)d_in[9];
    const float* b2  = (const float*)d_in[10];
    const float* g2  = (const float*)d_in[11];
    const float* be2 = (const float*)d_in[12];
    const float* m2  = (const float*)d_in[13];
    const float* v2  = (const float*)d_in[14];
    const float* Wc  = (const float*)d_in[15];
    const float* bc  = (const float*)d_in[16];
    float* out = (float*)d_out;

    int N = in_sizes[0] / D;
    int E = in_sizes[1] / 2;
    const int* src = ei;
    const int* dst = ei + E;

    __half *hH, *hG;
    cudaGetSymbolAddress((void**)&hH, g_hH);
    cudaGetSymbolAddress((void**)&hG, g_hG);

    int nb_fill   = (E + 1023) / 1024;
    int nb_node8  = (int)(((long long)N * 8 + 255) / 256);
    int nb_gemm1  = (N + 63) / 64;
    int nb_gemm2  = (N + 127) / 128;
    int nblk_scan = (N + 1023) / 1024;   // 98 <= 148, co-resident for gbar

    static cudaStream_t s2 = nullptr;
    static cudaEvent_t eFork = nullptr, eJoin = nullptr;
    if (!s2) {
        cudaStreamCreateWithFlags(&s2, cudaStreamNonBlocking);
        cudaEventCreateWithFlags(&eFork, cudaEventDisableTiming);
        cudaEventCreateWithFlags(&eJoin, cudaEventDisableTiming);
    }

    // fork: GEMM1 on s2 runs concurrently with cntscan+fill on default stream
    cudaEventRecord(eFork, 0);
    cudaStreamWaitEvent(s2, eFork, 0);
    k_gemm1<<<nb_gemm1, 256, 0, s2>>>(x, W1, hH, N);          // #1
    cudaEventRecord(eJoin, s2);

    k_cntscan<<<nblk_scan, 256>>>(dst, b1, g1, be1, m1, v1,
                                  b2, g2, be2, m2, v2, N, E, nblk_scan); // #2
    k_fill<<<nb_fill, 256>>>(src, dst, E);                    // #3

    cudaStreamWaitEvent(0, eJoin, 0);                         // join

    // #4 (PROFILED): layer-1 gather + BN1 + ReLU
    k_agg1<<<nb_node8, 256>>>(N);

    // #5: tensor-core GEMM(W2), dinv-scaled fp16 out
    k_gemm2tc<<<nb_gemm2, 256>>>(hG, W2, hH, N);

    // #6: layer-2 gather + BN2 + ReLU + pool + fused classifier
    k_agg2cls<<<nb_node8, 256>>>(bat, Wc, bc, out, N);
}

// round 16
// speedup vs baseline: 1.5876x; 1.5876x over previous
#include <cuda_runtime.h>
#include <cuda_fp16.h>

#define NMAX   100000
#define EMAX   1200000
#define NGRAPH 64
#define D      64
#define NBLK_SCAN 128   // >= ceil(NMAX/1024)

// ---------------- device scratch (no allocations allowed) ----------------
// INVARIANT at entry of every call: g_cntI==0, g_pooled==0, g_cnt==0, g_done==0,
// g_barCnt==0. g_barGen is monotonic (never reset; output-invariant).
// g_lbFlag is reset by k_csr phase 0 before the scan phase reads it.
__device__ __align__(16) __half g_hH[(size_t)NMAX * D];   // pre-agg rows (fp16)
__device__ __align__(16) __half g_hG[(size_t)NMAX * D];   // h1 rows (fp16)
__device__ float g_dinv[NMAX];
__device__ __align__(16) float g_pooled[NGRAPH * D];
__device__ float g_cnt[NGRAPH];
__device__ float g_sc1[D], g_sh1[D], g_sc2[D], g_sh2[D];

__device__ int g_cntI[NMAX];
__device__ int g_offs[NMAX + 1];
__device__ int g_cursor[NMAX];
__device__ __align__(16) int g_csrc[EMAX];
__device__ volatile unsigned g_lbFlag[NBLK_SCAN];  // status(2b)<<30 | sum
__device__ unsigned g_done;
__device__ unsigned g_barCnt;
__device__ volatile unsigned g_barGen;

// ------- grid barrier (grid sized by occupancy => all blocks co-resident) --
__device__ __forceinline__ void gbar(int NB) {
    __syncthreads();
    if (threadIdx.x == 0) {
        __threadfence();
        unsigned gen = g_barGen;
        unsigned t = atomicAdd(&g_barCnt, 1u);
        if (t == (unsigned)NB - 1u) {
            g_barCnt = 0;
            __threadfence();
            g_barGen = gen + 1u;
        } else {
            while (g_barGen == gen) __nanosleep(64);
        }
        __threadfence();
    }
    __syncthreads();
}

__device__ __forceinline__ void red_add_v4(float* addr, float a, float b,
                                           float c, float d) {
    asm volatile("red.global.add.v4.f32 [%0], {%1,%2,%3,%4};"
                 :: "l"(addr), "f"(a), "f"(b), "f"(c), "f"(d) : "memory");
}

__device__ __forceinline__ void red_add_i(int* addr, int v) {
    asm volatile("red.global.add.s32 [%0], %1;" :: "l"(addr), "r"(v) : "memory");
}

__device__ __forceinline__ float2 h2f(unsigned raw) {
    return __half22float2(*(__half2*)&raw);
}

__device__ __forceinline__ unsigned f2h(float a, float b) {
    __half2 p = __floats2half2_rn(a, b);
    return *(unsigned*)&p;
}

__device__ __forceinline__ uint2 f4_to_h4(float a, float b, float c, float d) {
    uint2 u;
    u.x = f2h(a, b);
    u.y = f2h(c, d);
    return u;
}

__device__ __forceinline__ void acc8_w(float* acc, uint4 r, float wt) {
    float2 p0 = h2f(r.x), p1 = h2f(r.y), p2 = h2f(r.z), p3 = h2f(r.w);
    acc[0] = fmaf(wt, p0.x, acc[0]); acc[1] = fmaf(wt, p0.y, acc[1]);
    acc[2] = fmaf(wt, p1.x, acc[2]); acc[3] = fmaf(wt, p1.y, acc[3]);
    acc[4] = fmaf(wt, p2.x, acc[4]); acc[5] = fmaf(wt, p2.y, acc[5]);
    acc[6] = fmaf(wt, p3.x, acc[6]); acc[7] = fmaf(wt, p3.y, acc[7]);
}

__device__ __forceinline__ void acc8(float* acc, uint4 r) {
    float2 p0 = h2f(r.x), p1 = h2f(r.y), p2 = h2f(r.z), p3 = h2f(r.w);
    acc[0] += p0.x; acc[1] += p0.y; acc[2] += p1.x; acc[3] += p1.y;
    acc[4] += p2.x; acc[5] += p2.y; acc[6] += p3.x; acc[7] += p3.y;
}

__device__ __forceinline__ void mma16816(float* c, unsigned a0, unsigned a1,
                                         unsigned a2, unsigned a3,
                                         unsigned b0, unsigned b1) {
    asm volatile(
        "mma.sync.aligned.m16n8k16.row.col.f32.f16.f16.f32 "
        "{%0,%1,%2,%3}, {%4,%5,%6,%7}, {%8,%9}, {%0,%1,%2,%3};"
        : "+f"(c[0]), "+f"(c[1]), "+f"(c[2]), "+f"(c[3])
        : "r"(a0), "r"(a1), "r"(a2), "r"(a3), "r"(b0), "r"(b1));
}

// ======= ONE-KERNEL CSR: cnt -> gbar -> scan -> gbar -> fill ================
// NB is occupancy-sized (>=NBLK_SCAN); cnt/fill grid-stride over full NB.
__global__ void __launch_bounds__(256) k_csr(
        const int* __restrict__ src, const int* __restrict__ dst,
        const float* __restrict__ b1, const float* __restrict__ g1,
        const float* __restrict__ be1, const float* __restrict__ m1,
        const float* __restrict__ v1,
        const float* __restrict__ b2, const float* __restrict__ g2,
        const float* __restrict__ be2, const float* __restrict__ m2,
        const float* __restrict__ v2,
        int N, int E, int NB, int nscan) {
    int tid = threadIdx.x, bid = blockIdx.x;

    // ---- phase 0: histogram (full grid) + lbFlag reset ----
    if (bid == 0 && tid < NBLK_SCAN) g_lbFlag[tid] = 0;
    {
        int stride4 = NB * 256 * 4;
        for (int e4 = (bid * 256 + tid) * 4; e4 < E; e4 += stride4) {
            if (e4 + 3 < E) {
                int4 d4 = *(const int4*)(dst + e4);
                red_add_i(&g_cntI[d4.x], 1);
                red_add_i(&g_cntI[d4.y], 1);
                red_add_i(&g_cntI[d4.z], 1);
                red_add_i(&g_cntI[d4.w], 1);
            } else {
                for (int e = e4; e < E; e++)
                    red_add_i(&g_cntI[dst[e]], 1);
            }
        }
    }
    gbar(NB);

    // ---- phase 1: decoupled look-back scan (blocks < nscan) ----
    if (bid < nscan) {
        __shared__ int wsum[8];
        __shared__ unsigned exS;
        __shared__ int totS;
        int lane = tid & 31, w = tid >> 5;
        int base = bid * 1024 + tid * 4;

        int v0 = 0, vv1 = 0, vv2 = 0, vv3 = 0;
        if (base + 0 < N) v0  = g_cntI[base + 0];
        if (base + 1 < N) vv1 = g_cntI[base + 1];
        if (base + 2 < N) vv2 = g_cntI[base + 2];
        if (base + 3 < N) vv3 = g_cntI[base + 3];
        int s = v0 + vv1 + vv2 + vv3;

        int inc = s;
#pragma unroll
        for (int o = 1; o < 32; o <<= 1) {
            int y = __shfl_up_sync(0xffffffff, inc, o);
            if (lane >= o) inc += y;
        }
        if (lane == 31) wsum[w] = inc;
        __syncthreads();
        if (tid == 0) {
            int run = 0;
#pragma unroll
            for (int i = 0; i < 8; i++) { int xv = wsum[i]; wsum[i] = run; run += xv; }
            totS = run;
            unsigned pack = (bid == 0 ? (2u << 30) : (1u << 30)) | (unsigned)run;
            atomicExch((unsigned*)&g_lbFlag[bid], pack);
        }
        __syncthreads();
        int blkEx = wsum[w] + inc - s;
        int total = totS;

        if (bid > 0) {
            if (w == 0) {
                unsigned ex = 0;
                int wnd = bid;
                for (;;) {
                    int idx = wnd - 32 + lane;
                    unsigned f = (1u << 30);
                    if (idx >= 0) {
                        do { f = g_lbFlag[idx]; } while ((f >> 30) == 0);
                    }
                    unsigned isPref = __ballot_sync(0xffffffff, idx >= 0 && (f >> 30) == 2u);
                    int cut = isPref ? (31 - __clz(isPref)) : -1;
                    unsigned val = (lane >= cut) ? (f & 0x3FFFFFFFu) : 0u;
#pragma unroll
                    for (int o = 16; o; o >>= 1) val += __shfl_down_sync(0xffffffff, val, o);
                    if (lane == 0) ex += val;
                    if (cut >= 0) break;
                    wnd -= 32;
                }
                if (lane == 0) {
                    exS = ex;
                    atomicExch((unsigned*)&g_lbFlag[bid], (2u << 30) | (ex + (unsigned)total));
                }
            }
            __syncthreads();
        } else if (tid == 0) {
            exS = 0;
        }
        __syncthreads();
        unsigned ex = exS;

        int o = (int)ex + blkEx;
        if (base + 0 < N) { g_offs[base+0]=o; g_cursor[base+0]=o; g_dinv[base+0]=rsqrtf((float)v0 +1.f); g_cntI[base+0]=0; o+=v0;  }
        if (base + 1 < N) { g_offs[base+1]=o; g_cursor[base+1]=o; g_dinv[base+1]=rsqrtf((float)vv1+1.f); g_cntI[base+1]=0; o+=vv1; }
        if (base + 2 < N) { g_offs[base+2]=o; g_cursor[base+2]=o; g_dinv[base+2]=rsqrtf((float)vv2+1.f); g_cntI[base+2]=0; o+=vv2; }
        if (base + 3 < N) { g_offs[base+3]=o; g_cursor[base+3]=o; g_dinv[base+3]=rsqrtf((float)vv3+1.f); g_cntI[base+3]=0; }

        if (bid == 0 && tid == 0) g_offs[N] = E;
        if (bid == 0 && tid < D) {
            float s1 = g1[tid] * rsqrtf(v1[tid] + 1e-5f);
            g_sc1[tid] = s1;
            g_sh1[tid] = (b1[tid] - m1[tid]) * s1 + be1[tid];
            float s2 = g2[tid] * rsqrtf(v2[tid] + 1e-5f);
            g_sc2[tid] = s2;
            g_sh2[tid] = (b2[tid] - m2[tid]) * s2 + be2[tid];
        }
    }
    gbar(NB);

    // ---- phase 2: CSR fill (full grid) ----
    {
        int stride4 = NB * 256 * 4;
        for (int e4 = (bid * 256 + tid) * 4; e4 < E; e4 += stride4) {
            if (e4 + 3 < E) {
                int4 d4 = *(const int4*)(dst + e4);
                int4 s4 = *(const int4*)(src + e4);
                int p0 = atomicAdd(&g_cursor[d4.x], 1);
                int p1 = atomicAdd(&g_cursor[d4.y], 1);
                int p2 = atomicAdd(&g_cursor[d4.z], 1);
                int p3 = atomicAdd(&g_cursor[d4.w], 1);
                g_csrc[p0] = s4.x;
                g_csrc[p1] = s4.y;
                g_csrc[p2] = s4.z;
                g_csrc[p3] = s4.w;
            } else {
                for (int e = e4; e < E; e++) {
                    int d = dst[e];
                    int p = atomicAdd(&g_cursor[d], 1);
                    g_csrc[p] = src[e];
                }
            }
        }
    }
}

// ---------------- GEMM1 core macro ----------------
#define GEMM_ROW(ai, i)                                                           \
    acc[i][0] = fmaf(ai.w, w3.x, fmaf(ai.z, w2.x, fmaf(ai.y, w1.x, fmaf(ai.x, w0.x, acc[i][0])))); \
    acc[i][1] = fmaf(ai.w, w3.y, fmaf(ai.z, w2.y, fmaf(ai.y, w1.y, fmaf(ai.x, w0.y, acc[i][1])))); \
    acc[i][2] = fmaf(ai.w, w3.z, fmaf(ai.z, w2.z, fmaf(ai.y, w1.z, fmaf(ai.x, w0.z, acc[i][2])))); \
    acc[i][3] = fmaf(ai.w, w3.w, fmaf(ai.z, w2.w, fmaf(ai.y, w1.w, fmaf(ai.x, w0.w, acc[i][3]))));

// ------- GEMM1: C_h[N,64] = fp16(A_f32 @ W1) (runs ∥ k_csr) ----------------
__global__ void __launch_bounds__(256) k_gemm1(const float* __restrict__ A,
                                               const float* __restrict__ W,
                                               __half* __restrict__ C, int N) {
    __shared__ __align__(16) float Ws[D * D];
    __shared__ __align__(16) float As[64 * 68];
    int tid = threadIdx.x;
    int row0 = blockIdx.x * 64;

    float4* Ws4 = (float4*)Ws;
    const float4* W4 = (const float4*)W;
#pragma unroll
    for (int i = 0; i < 4; i++) Ws4[tid + i * 256] = W4[tid + i * 256];

#pragma unroll
    for (int i = 0; i < 4; i++) {
        int idx = tid + i * 256;
        int r = idx >> 4, c4 = idx & 15;
        float4 a = make_float4(0.f, 0.f, 0.f, 0.f);
        if (row0 + r < N)
            a = __ldcs((const float4*)(A + (size_t)(row0 + r) * D) + c4);
        ((float4*)&As[r * 68])[c4] = a;
    }
    __syncthreads();

    int tx = tid & 15, ty = tid >> 4;
    float acc[4][4];
#pragma unroll
    for (int i = 0; i < 4; i++)
#pragma unroll
        for (int j = 0; j < 4; j++) acc[i][j] = 0.f;

    const float4* A0 = (const float4*)&As[(ty * 4 + 0) * 68];
    const float4* A1 = (const float4*)&As[(ty * 4 + 1) * 68];
    const float4* A2 = (const float4*)&As[(ty * 4 + 2) * 68];
    const float4* A3 = (const float4*)&As[(ty * 4 + 3) * 68];

#pragma unroll
    for (int k4 = 0; k4 < 16; k4++) {
        float4 w0 = Ws4[(4 * k4 + 0) * 16 + tx];
        float4 w1 = Ws4[(4 * k4 + 1) * 16 + tx];
        float4 w2 = Ws4[(4 * k4 + 2) * 16 + tx];
        float4 w3 = Ws4[(4 * k4 + 3) * 16 + tx];
        float4 a0 = A0[k4], a1 = A1[k4], a2 = A2[k4], a3 = A3[k4];
        GEMM_ROW(a0, 0)
        GEMM_ROW(a1, 1)
        GEMM_ROW(a2, 2)
        GEMM_ROW(a3, 3)
    }

#pragma unroll
    for (int i = 0; i < 4; i++) {
        int r = row0 + ty * 4 + i;
        if (r < N)
            ((uint2*)(C + (size_t)r * D))[tx] =
                f4_to_h4(acc[i][0], acc[i][1], acc[i][2], acc[i][3]);
    }
}

// -------- layer-1 gather: 8 threads/node, uint4 (16B) lanes ----------------
__global__ void __launch_bounds__(256) k_agg1(int N) {
    int t = blockIdx.x * blockDim.x + threadIdx.x;
    int node = t >> 3;
    if (node >= N) return;
    int c8 = t & 7;
    const uint4* hp = (const uint4*)g_hH;   // row = 8 uint4
    float dd = g_dinv[node];
    float acc[8];
    {
        uint4 sr = hp[(size_t)node * 8 + c8];
        float2 p0 = h2f(sr.x), p1 = h2f(sr.y), p2 = h2f(sr.z), p3 = h2f(sr.w);
        acc[0] = dd * p0.x; acc[1] = dd * p0.y;
        acc[2] = dd * p1.x; acc[3] = dd * p1.y;
        acc[4] = dd * p2.x; acc[5] = dd * p2.y;
        acc[6] = dd * p3.x; acc[7] = dd * p3.y;
    }
    int beg = g_offs[node], end = g_offs[node + 1];
    int j = beg;
    for (; j + 3 < end; j += 4) {
        int i0 = __ldg(&g_csrc[j + 0]);
        int i1 = __ldg(&g_csrc[j + 1]);
        int i2 = __ldg(&g_csrc[j + 2]);
        int i3 = __ldg(&g_csrc[j + 3]);
        float w0 = __ldg(&g_dinv[i0]);
        float w1 = __ldg(&g_dinv[i1]);
        float w2 = __ldg(&g_dinv[i2]);
        float w3 = __ldg(&g_dinv[i3]);
        uint4 r0 = __ldg(&hp[(size_t)i0 * 8 + c8]);
        uint4 r1 = __ldg(&hp[(size_t)i1 * 8 + c8]);
        uint4 r2 = __ldg(&hp[(size_t)i2 * 8 + c8]);
        uint4 r3 = __ldg(&hp[(size_t)i3 * 8 + c8]);
        acc8_w(acc, r0, w0);
        acc8_w(acc, r1, w1);
        acc8_w(acc, r2, w2);
        acc8_w(acc, r3, w3);
    }
    for (; j < end; j++) {
        int i0 = __ldg(&g_csrc[j]);
        float w0 = __ldg(&g_dinv[i0]);
        uint4 r0 = __ldg(&hp[(size_t)i0 * 8 + c8]);
        acc8_w(acc, r0, w0);
    }
    int c = c8 * 8;
    uint4 outv;
    {
        float y0 = fmaxf(0.f, acc[0] * dd * g_sc1[c + 0] + g_sh1[c + 0]);
        float y1 = fmaxf(0.f, acc[1] * dd * g_sc1[c + 1] + g_sh1[c + 1]);
        float y2 = fmaxf(0.f, acc[2] * dd * g_sc1[c + 2] + g_sh1[c + 2]);
        float y3 = fmaxf(0.f, acc[3] * dd * g_sc1[c + 3] + g_sh1[c + 3]);
        float y4 = fmaxf(0.f, acc[4] * dd * g_sc1[c + 4] + g_sh1[c + 4]);
        float y5 = fmaxf(0.f, acc[5] * dd * g_sc1[c + 5] + g_sh1[c + 5]);
        float y6 = fmaxf(0.f, acc[6] * dd * g_sc1[c + 6] + g_sh1[c + 6]);
        float y7 = fmaxf(0.f, acc[7] * dd * g_sc1[c + 7] + g_sh1[c + 7]);
        outv.x = f2h(y0, y1); outv.y = f2h(y2, y3);
        outv.z = f2h(y4, y5); outv.w = f2h(y6, y7);
    }
    ((uint4*)g_hG)[(size_t)node * 8 + c8] = outv;
}

// ------- GEMM2 tensor-core: hH = fp16((hG @ W2) * dinv), W2 split hi+res ---
__global__ void __launch_bounds__(256) k_gemm2tc(const __half* __restrict__ A,
                                                 const float* __restrict__ W,
                                                 __half* __restrict__ C, int N) {
    __shared__ __align__(16) __half As[128 * 72];
    __shared__ __align__(16) __half Wh[64 * 72];
    __shared__ __align__(16) __half Wr[64 * 72];
    int tid = threadIdx.x;
    int warp = tid >> 5, lane = tid & 31;
    int row0 = blockIdx.x * 128;

#pragma unroll
    for (int i = 0; i < 16; i++) {
        int idx = tid + i * 256;
        int k = idx >> 6, n = idx & 63;
        float w = W[k * 64 + n];
        __half wh = __float2half_rn(w);
        Wh[n * 72 + k] = wh;
        Wr[n * 72 + k] = __float2half_rn(w - __half2float(wh));
    }

#pragma unroll
    for (int i = 0; i < 4; i++) {
        int idx = tid + i * 256;
        int r = idx >> 3, c8 = idx & 7;
        uint4 raw = make_uint4(0u, 0u, 0u, 0u);
        if (row0 + r < N)
            raw = __ldcs((const uint4*)(A + (size_t)(row0 + r) * D) + c8);
        *(uint4*)&As[r * 72 + c8 * 8] = raw;
    }
    __syncthreads();

    int g = lane >> 2, tg = lane & 3;
    int rbase = warp * 16;
    float acc[8][4];
#pragma unroll
    for (int nt = 0; nt < 8; nt++)
#pragma unroll
        for (int i = 0; i < 4; i++) acc[nt][i] = 0.f;

#pragma unroll
    for (int k0 = 0; k0 < 64; k0 += 16) {
        unsigned ra0 = *(const unsigned*)&As[(rbase + g) * 72 + k0 + tg * 2];
        unsigned ra1 = *(const unsigned*)&As[(rbase + g + 8) * 72 + k0 + tg * 2];
        unsigned ra2 = *(const unsigned*)&As[(rbase + g) * 72 + k0 + tg * 2 + 8];
        unsigned ra3 = *(const unsigned*)&As[(rbase + g + 8) * 72 + k0 + tg * 2 + 8];
#pragma unroll
        for (int nt = 0; nt < 8; nt++) {
            int nrow = (nt * 8 + g) * 72 + k0 + tg * 2;
            unsigned bh0 = *(const unsigned*)&Wh[nrow];
            unsigned bh1 = *(const unsigned*)&Wh[nrow + 8];
            mma16816(acc[nt], ra0, ra1, ra2, ra3, bh0, bh1);
            unsigned br0 = *(const unsigned*)&Wr[nrow];
            unsigned br1 = *(const unsigned*)&Wr[nrow + 8];
            mma16816(acc[nt], ra0, ra1, ra2, ra3, br0, br1);
        }
    }

    int r0g = row0 + rbase + g;
    int r1g = r0g + 8;
    float d0 = (r0g < N) ? g_dinv[r0g] : 0.f;
    float d1 = (r1g < N) ? g_dinv[r1g] : 0.f;
#pragma unroll
    for (int nt = 0; nt < 8; nt++) {
        int n = nt * 8 + tg * 2;
        if (r0g < N)
            *(unsigned*)(C + (size_t)r0g * D + n) = f2h(acc[nt][0] * d0, acc[nt][1] * d0);
        if (r1g < N)
            *(unsigned*)(C + (size_t)r1g * D + n) = f2h(acc[nt][2] * d1, acc[nt][3] * d1);
    }
}

// ------- agg2 (8T/node) + BN2 + ReLU + warp-reduced pool + classifier ------
__global__ void __launch_bounds__(256) k_agg2cls(const int* __restrict__ batch,
                                                 const float* __restrict__ Wc,
                                                 const float* __restrict__ bc,
                                                 float* __restrict__ out, int N) {
    __shared__ int isLast;
    int t = blockIdx.x * blockDim.x + threadIdx.x;
    int tid = threadIdx.x;
    int lane = tid & 31;
    int node = t >> 3;
    bool valid = (node < N);
    int c8 = t & 7;

    float y[8];
#pragma unroll
    for (int i = 0; i < 8; i++) y[i] = 0.f;
    int g = batch[valid ? node : (N - 1)];

    if (valid) {
        const uint4* hp = (const uint4*)g_hH;
        float acc[8];
        {
            uint4 sr = hp[(size_t)node * 8 + c8];
            float2 p0 = h2f(sr.x), p1 = h2f(sr.y), p2 = h2f(sr.z), p3 = h2f(sr.w);
            acc[0] = p0.x; acc[1] = p0.y; acc[2] = p1.x; acc[3] = p1.y;
            acc[4] = p2.x; acc[5] = p2.y; acc[6] = p3.x; acc[7] = p3.y;
        }
        int beg = g_offs[node], end = g_offs[node + 1];
        int j = beg;
        for (; j + 3 < end; j += 4) {
            int i0 = __ldg(&g_csrc[j + 0]);
            int i1 = __ldg(&g_csrc[j + 1]);
            int i2 = __ldg(&g_csrc[j + 2]);
            int i3 = __ldg(&g_csrc[j + 3]);
            uint4 r0 = __ldg(&hp[(size_t)i0 * 8 + c8]);
            uint4 r1 = __ldg(&hp[(size_t)i1 * 8 + c8]);
            uint4 r2 = __ldg(&hp[(size_t)i2 * 8 + c8]);
            uint4 r3 = __ldg(&hp[(size_t)i3 * 8 + c8]);
            acc8(acc, r0);
            acc8(acc, r1);
            acc8(acc, r2);
            acc8(acc, r3);
        }
        for (; j < end; j++) {
            int i0 = __ldg(&g_csrc[j]);
            uint4 r0 = __ldg(&hp[(size_t)i0 * 8 + c8]);
            acc8(acc, r0);
        }
        float dd = g_dinv[node];
        int c = c8 * 8;
#pragma unroll
        for (int i = 0; i < 8; i++)
            y[i] = fmaxf(0.f, acc[i] * dd * g_sc2[c + i] + g_sh2[c + i]);
    }

    // warp-level pool reduction: 4 nodes per warp, usually same graph
    int g0 = __shfl_sync(0xffffffffu, g, 0);
    bool uni = __all_sync(0xffffffffu, g == g0);
    unsigned vball = __ballot_sync(0xffffffffu, valid && c8 == 0);
    if (uni) {
#pragma unroll
        for (int i = 0; i < 8; i++) {
            y[i] += __shfl_xor_sync(0xffffffffu, y[i], 8);
            y[i] += __shfl_xor_sync(0xffffffffu, y[i], 16);
        }
        if (lane < 8 && vball) {
            int c = lane * 8;
            red_add_v4(&g_pooled[g0 * D + c + 0], y[0], y[1], y[2], y[3]);
            red_add_v4(&g_pooled[g0 * D + c + 4], y[4], y[5], y[6], y[7]);
        }
        if (lane == 0 && vball)
            atomicAdd(&g_cnt[g0], (float)__popc(vball));
    } else {
        if (valid) {
            int c = c8 * 8;
            red_add_v4(&g_pooled[g * D + c + 0], y[0], y[1], y[2], y[3]);
            red_add_v4(&g_pooled[g * D + c + 4], y[4], y[5], y[6], y[7]);
            if (c8 == 0) atomicAdd(&g_cnt[g], 1.0f);
        }
    }

    // last-block-does-classifier
    __threadfence();
    __syncthreads();
    if (tid == 0) {
        unsigned old = atomicAdd(&g_done, 1u);
        isLast = (old == gridDim.x - 1u) ? 1 : 0;
    }
    __syncthreads();
    if (isLast) {
        __threadfence();
        if (tid < NGRAPH * 2) {
            int gg = tid >> 1, o = tid & 1;
            float inv = 1.f / fmaxf(g_cnt[gg], 1.f);
            float s = 0.f;
#pragma unroll
            for (int d = 0; d < D; d++) s += g_pooled[gg * D + d] * Wc[d * 2 + o];
            out[tid] = s * inv + bc[o];
        }
        __syncthreads();
        for (int i = tid; i < NGRAPH * D; i += 256) g_pooled[i] = 0.f;
        if (tid < NGRAPH) g_cnt[tid] = 0.f;
        if (tid == 0) g_done = 0;
    }
}

// ---------------- host orchestration (fork/join, 5 launches) ---------------
extern "C" void kernel_launch(void* const* d_in, const int* in_sizes, int n_in,
                              void* d_out, int out_size) {
    const float* x   = (const float*)d_in[0];
    const int*   ei  = (const int*)d_in[1];
    const int*   bat = (const int*)d_in[2];
    const float* W1  = (const float*)d_in[3];
    const float* b1  = (const float*)d_in[4];
    const float* g1  = (const float*)d_in[5];
    const float* be1 = (const float*)d_in[6];
    const float* m1  = (const float*)d_in[7];
    const float* v1  = (const float*)d_in[8];
    const float* W2  = (const float*)d_in[9];
    const float* b2  = (const float*)d_in[10];
    const float* g2  = (const float*)d_in[11];
    const float* be2 = (const float*)d_in[12];
    const float* m2  = (const float*)d_in[13];
    const float* v2  = (const float*)d_in[14];
    const float* Wc  = (const float*)d_in[15];
    const float* bc  = (const float*)d_in[16];
    float* out = (float*)d_out;

    int N = in_sizes[0] / D;
    int E = in_sizes[1] / 2;
    const int* src = ei;
    const int* dst = ei + E;

    __half *hH, *hG;
    cudaGetSymbolAddress((void**)&hH, g_hH);
    cudaGetSymbolAddress((void**)&hG, g_hG);

    int nb_node8  = (int)(((long long)N * 8 + 255) / 256);
    int nb_gemm1  = (N + 63) / 64;
    int nb_gemm2  = (N + 127) / 128;
    int nscan     = (N + 1023) / 1024;   // 98 scan tiles

    static cudaStream_t s2 = nullptr;
    static cudaEvent_t eFork = nullptr, eJoin = nullptr;
    static int NB_CSR = 0;
    if (!s2) {
        cudaStreamCreateWithFlags(&s2, cudaStreamNonBlocking);
        cudaEventCreateWithFlags(&eFork, cudaEventDisableTiming);
        cudaEventCreateWithFlags(&eJoin, cudaEventDisableTiming);
        int dev = 0, nsm = 0, bpm = 0;
        cudaGetDevice(&dev);
        cudaDeviceGetAttribute(&nsm, cudaDevAttrMultiProcessorCount, dev);
        cudaOccupancyMaxActiveBlocksPerMultiprocessor(&bpm, k_csr, 256, 0);
        if (bpm < 1) bpm = 1;
        NB_CSR = nsm * bpm;
        if (NB_CSR < NBLK_SCAN) NB_CSR = NBLK_SCAN;   // need scan tiles resident
        if (NB_CSR > 1184) NB_CSR = 1184;
    }

    // fork: GEMM1 on s2 runs concurrently with k_csr on default stream
    cudaEventRecord(eFork, 0);
    cudaStreamWaitEvent(s2, eFork, 0);
    k_gemm1<<<nb_gemm1, 256, 0, s2>>>(x, W1, hH, N);          // #1
    cudaEventRecord(eJoin, s2);

    // #2: cnt -> scan -> fill in one kernel (occupancy-sized grid)
    k_csr<<<NB_CSR, 256>>>(src, dst, b1, g1, be1, m1, v1,
                           b2, g2, be2, m2, v2, N, E, NB_CSR, nscan);

    cudaStreamWaitEvent(0, eJoin, 0);                         // join

    // #3: layer-1 gather + BN1 + ReLU
    k_agg1<<<nb_node8, 256>>>(N);

    // #4 (PROFILED): tensor-core GEMM(W2), dinv-scaled fp16 out
    k_gemm2tc<<<nb_gemm2, 256>>>(hG, W2, hH, N);

    // #5: layer-2 gather + BN2 + ReLU + warp-reduced pool + classifier
    k_agg2cls<<<nb_node8, 256>>>(bat, Wc, bc, out, N);
}